// round 13
// baseline (speedup 1.0000x reference)
#include <cuda_runtime.h>

#define NQ       12
#define DIM      4096            // 2^12
#define NLAYERS  6
#define NGATES   (NLAYERS * NQ)  // 72
#define THREADS  128
#define APT      (DIM / THREADS) // 32 amplitudes per thread

typedef unsigned long long ull;

// Linear, invertible address swizzle; for every pass type the 5 lane-varying
// rep bits map injectively into address bits 0-4 -> conflict-free 32-bit LDS/STS.
__device__ __forceinline__ unsigned S2(unsigned p) {
    return p ^ ((p >> 4) & 0xFu) ^ (((p >> 8) & 1u) << 4);
}

// GF(2) matrices of the CNOT-chain map per layer (verified: rowA.colB = I,
// leading bit of cCOLB[l][q] is q). cROWA[l][j] = row j of T^l; cCOLB = col of T^-l.
__constant__ unsigned cROWA[NLAYERS + 1][NQ] = {
    {0x001,0x002,0x004,0x008,0x010,0x020,0x040,0x080,0x100,0x200,0x400,0x800},
    {0xFFF,0xFFE,0xFFC,0xFF8,0xFF0,0xFE0,0xFC0,0xF80,0xF00,0xE00,0xC00,0x800},
    {0x555,0xAAA,0x554,0xAA8,0x550,0xAA0,0x540,0xA80,0x500,0xA00,0x400,0x800},
    {0x333,0x666,0xCCC,0x998,0x330,0x660,0xCC0,0x980,0x300,0x600,0xC00,0x800},
    {0x111,0x222,0x444,0x888,0x110,0x220,0x440,0x880,0x100,0x200,0x400,0x800},
    {0xF0F,0xE1E,0xC3C,0x878,0x0F0,0x1E0,0x3C0,0x780,0xF00,0xE00,0xC00,0x800},
    {0x505,0xA0A,0x414,0x828,0x050,0x0A0,0x140,0x280,0x500,0xA00,0x400,0x800},
};
__constant__ unsigned cCOLB[NLAYERS][NQ] = {
    {0x001,0x002,0x004,0x008,0x010,0x020,0x040,0x080,0x100,0x200,0x400,0x800},
    {0x001,0x003,0x006,0x00C,0x018,0x030,0x060,0x0C0,0x180,0x300,0x600,0xC00},
    {0x001,0x002,0x005,0x00A,0x014,0x028,0x050,0x0A0,0x140,0x280,0x500,0xA00},
    {0x001,0x003,0x007,0x00F,0x01E,0x03C,0x078,0x0F0,0x1E0,0x3C0,0x780,0xF00},
    {0x001,0x002,0x004,0x008,0x011,0x022,0x044,0x088,0x110,0x220,0x440,0x880},
    {0x001,0x003,0x006,0x00C,0x019,0x033,0x066,0x0CC,0x198,0x330,0x660,0xCC0},
};

// ---- packed f32x2 primitives ----
__device__ __forceinline__ ull f2mul(ull a, ull b) {
    ull d; asm("mul.rn.f32x2 %0, %1, %2;" : "=l"(d) : "l"(a), "l"(b)); return d;
}
__device__ __forceinline__ ull f2fma(ull a, ull b, ull c) {
    ull d; asm("fma.rn.f32x2 %0, %1, %2, %3;" : "=l"(d) : "l"(a), "l"(b), "l"(c)); return d;
}
__device__ __forceinline__ ull f2swap(ull v) {  // (lo,hi) -> (hi,lo)
    ull d;
    asm("{\n\t.reg .b32 lo, hi;\n\tmov.b64 {lo, hi}, %1;\n\tmov.b64 %0, {hi, lo};\n\t}"
        : "=l"(d) : "l"(v));
    return d;
}
__device__ __forceinline__ ull packf2(float lo, float hi) {
    ull r; asm("mov.b64 %0, {%1, %2};" : "=l"(r) : "f"(lo), "f"(hi)); return r;
}
__device__ __forceinline__ void unpk2(ull v, float& lo, float& hi) {
    asm("mov.b64 {%0, %1}, %2;" : "=f"(lo), "=f"(hi) : "l"(v));
}

// ABC-role gate (pairs two plane-register pairs; lanes = two members of the
// SAME group, same orientation c). No swaps. Words (broadcast (x,x)):
// w0=g00r, w1=g00i, w2=-g00i, w3=g01r, w4=-g01r, w5=g01i, w6=-g01i.
// Orientation c=1 substitutes g00i->-g00i (idx 1+c), g01r->-g01r (idx 3+c).
__device__ __forceinline__ void abc(ull& x0re, ull& x0im, ull& x1re, ull& x1im,
                                    ull w0, ull gi, ull gin, ull gr1, ull gr1n,
                                    ull w5, ull w6) {
    ull y0re = f2fma(w0, x0re, f2fma(gin,  x0im, f2fma(gr1, x1re, f2mul(w6,  x1im))));
    ull y0im = f2fma(gi, x0re, f2fma(w0,   x0im, f2fma(w5,  x1re, f2mul(gr1, x1im))));
    ull y1re = f2fma(gr1n, x0re, f2fma(w6,   x0im, f2fma(w0,  x1re, f2mul(gi, x1im))));
    ull y1im = f2fma(w5,   x0re, f2fma(gr1n, x0im, f2fma(gin, x1re, f2mul(w0, x1im))));
    x0re = y0re; x0im = y0im; x1re = y1re; x1im = y1im;
}

// D-role gate (butterfly WITHIN the packed lanes). Words:
// t0=P1=(g00r,g00r), t1=P2=(g01r,-g01r), t2=-P2, t3=P3=(-g00i,g00i), t4=-P3,
// t5=P4=(-g01i,-g01i), t6=-P4.  yre = P1.xre + w[1+c].xres + w[3+c].xim + t5.xims
//                               yim = w[4-c].xre + t6.xres + P1.xim + w[1+c].xims
__device__ __forceinline__ void dgate(ull& xre, ull& xim,
                                      ull p1, ull p2e, ull p3e, ull p3n,
                                      ull p4, ull p4n) {
    ull xres = f2swap(xre), xims = f2swap(xim);
    ull yre = f2fma(p1,  xre, f2fma(p2e, xres, f2fma(p3e, xim, f2mul(p4,  xims))));
    ull yim = f2fma(p3n, xre, f2fma(p4n, xres, f2fma(p1,  xim, f2mul(p2e, xims))));
    xre = yre; xim = yim;
}

__global__ __launch_bounds__(THREADS, 6)
void qsim_kernel(const float* __restrict__ x,
                 const float* __restrict__ params,
                 float* __restrict__ out) {
    __shared__ float  sRe[DIM], sIm[DIM];   // 32 KB plane-split statevector, S2 layout
    __shared__ ull    sTab[NGATES * 7];     // 4 KB packed gate words (role-dependent)
    __shared__ float  sc[NQ], ssn[NQ];      // cos(x/2), sin(x/2)
    __shared__ float2 sL[32];               // product table, qubits 7..11
    __shared__ float  sExp[NQ];             // <Z_q> accumulators

    const int tid = threadIdx.x;
    const int b   = blockIdx.x;

    // ---- stage 0: trig + packed gate tables ----
    if (tid < NQ) {
        float xv = x[b * NQ + tid];
        sc[tid]   = cosf(0.5f * xv);
        ssn[tid]  = sinf(0.5f * xv);
        sExp[tid] = 0.0f;
    }
    if (tid < NGATES) {
        float phi = params[tid * 3 + 0];
        float th  = params[tid * 3 + 1];
        float om  = params[tid * 3 + 2];
        float ct = cosf(0.5f * th), st = sinf(0.5f * th);
        float aa = 0.5f * (phi + om), bb = 0.5f * (phi - om);
        float ca = cosf(aa), sa = sinf(aa);
        float cb = cosf(bb), sb = sinf(bb);
        // G00 = (g00r, g00i) = (ca ct, -sa ct); G01 = (g01r, g01i) = (-cb st, -sb st)
        float g00r = ca * ct,  g00i = -sa * ct;
        float g01r = -cb * st, g01i = -sb * st;
        int tb = tid * 7;
        if ((tid % 4) != 3) {   // ABC-role: broadcast words
            sTab[tb + 0] = packf2( g00r,  g00r);
            sTab[tb + 1] = packf2( g00i,  g00i);
            sTab[tb + 2] = packf2(-g00i, -g00i);
            sTab[tb + 3] = packf2( g01r,  g01r);
            sTab[tb + 4] = packf2(-g01r, -g01r);
            sTab[tb + 5] = packf2( g01i,  g01i);
            sTab[tb + 6] = packf2(-g01i, -g01i);
        } else {                // D-role: lane-asymmetric words
            sTab[tb + 0] = packf2( g00r,  g00r);   // P1
            sTab[tb + 1] = packf2( g01r, -g01r);   // P2
            sTab[tb + 2] = packf2(-g01r,  g01r);   // -P2
            sTab[tb + 3] = packf2(-g00i,  g00i);   // P3
            sTab[tb + 4] = packf2( g00i, -g00i);   // -P3
            sTab[tb + 5] = packf2(-g01i, -g01i);   // P4
            sTab[tb + 6] = packf2( g01i,  g01i);   // -P4
        }
    }
    __syncthreads();

    // ---- stage 1: low-5-bit product table (qubits 7..11 <-> bits 4..0) ----
    if (tid < 32) {
        float2 v = make_float2(1.0f, 0.0f);
        #pragma unroll
        for (int j = 0; j < 5; j++) {
            int q   = 7 + j;
            int bit = (tid >> (4 - j)) & 1;
            v = bit ? make_float2(v.y * ssn[q], -v.x * ssn[q])  // v * (-i sin)
                    : make_float2(v.x * sc[q],   v.y * sc[q]);  // v * cos
        }
        sL[tid] = v;
    }
    __syncthreads();

    // ---- stage 2: direct product-state init (RX embedding on |0..0>) ----
    {
        float2 h = make_float2(1.0f, 0.0f);
        #pragma unroll
        for (int j = 0; j < 7; j++) {
            int bit = (tid >> (6 - j)) & 1;
            h = bit ? make_float2(h.y * ssn[j], -h.x * ssn[j])
                    : make_float2(h.x * sc[j],   h.y * sc[j]);
        }
        #pragma unroll
        for (int lo = 0; lo < 32; lo++) {
            unsigned p = tid * APT + lo;
            float2 g = sL[lo];
            unsigned idx = S2(p);
            sRe[idx] = fmaf(h.x, g.x, -h.y * g.y);
            sIm[idx] = fmaf(h.x, g.y,  h.y * g.x);
        }
    }
    __syncthreads();

    // ---- stage 3: variational layers; 4 gates fused, CNOTs folded into masks ----
    // Invariant entering layer l: sPhys[p] = sLogical[(T^l) p].
    // Register r holds members (2r, 2r+1) of a 16-member coset group.
    for (int l = 0; l < NLAYERS; l++) {
        #pragma unroll
        for (int qp = 0; qp < NQ; qp += 4) {
            const int jA = 11 - qp;
            const int pb = 8 - qp;                 // pivot block low bit: 8,4,0
            const unsigned rA = cROWA[l][jA],     rB = cROWA[l][jA - 1];
            const unsigned rC = cROWA[l][jA - 2], rD = cROWA[l][jA - 3];
            const unsigned wA = S2(cCOLB[l][jA]),     wB = S2(cCOLB[l][jA - 1]);
            const unsigned wC = S2(cCOLB[l][jA - 2]), wD = S2(cCOLB[l][jA - 3]);
            const unsigned lomask = (pb > 0) ? ((1u << pb) - 1u) : 0u;
            const int t7 = (l * NQ + qp) * 7;      // table base (gate A)

            #pragma unroll
            for (int it = 0; it < DIM / 16 / THREADS; it++) {  // 2 groups/thread
                unsigned g   = tid + it * THREADS;             // 8-bit coset id
                unsigned rep = ((g >> pb) << (pb + 4)) | (g & lomask);
                const unsigned sb = S2(rep);
                const unsigned cA = __popc(rA & rep) & 1u;
                const unsigned cB = __popc(rB & rep) & 1u;
                const unsigned cC = __popc(rC & rep) & 1u;
                const unsigned cD = __popc(rD & rep) & 1u;

                ull vre[8], vim[8];
                #pragma unroll
                for (int r = 0; r < 8; r++) {
                    unsigned a = sb ^ ((r & 4) ? wA : 0u) ^ ((r & 2) ? wB : 0u)
                                    ^ ((r & 1) ? wC : 0u);
                    vre[r] = packf2(sRe[a], sRe[a ^ wD]);
                    vim[r] = packf2(sIm[a], sIm[a ^ wD]);
                }
                {   // gate A (member bit 3 <-> reg bit 2)
                    ull w0 = sTab[t7 + 0], gi = sTab[t7 + 1 + cA], gin = sTab[t7 + 2 - cA];
                    ull g1 = sTab[t7 + 3 + cA], g1n = sTab[t7 + 4 - cA];
                    ull w5 = sTab[t7 + 5], w6 = sTab[t7 + 6];
                    #pragma unroll
                    for (int r = 0; r < 4; r++)
                        abc(vre[r], vim[r], vre[r + 4], vim[r + 4],
                            w0, gi, gin, g1, g1n, w5, w6);
                }
                {   // gate B (reg bit 1)
                    const int t = t7 + 7;
                    ull w0 = sTab[t + 0], gi = sTab[t + 1 + cB], gin = sTab[t + 2 - cB];
                    ull g1 = sTab[t + 3 + cB], g1n = sTab[t + 4 - cB];
                    ull w5 = sTab[t + 5], w6 = sTab[t + 6];
                    #pragma unroll
                    for (int h = 0; h < 8; h += 4)
                        #pragma unroll
                        for (int r = 0; r < 2; r++)
                            abc(vre[h + r], vim[h + r], vre[h + r + 2], vim[h + r + 2],
                                w0, gi, gin, g1, g1n, w5, w6);
                }
                {   // gate C (reg bit 0)
                    const int t = t7 + 14;
                    ull w0 = sTab[t + 0], gi = sTab[t + 1 + cC], gin = sTab[t + 2 - cC];
                    ull g1 = sTab[t + 3 + cC], g1n = sTab[t + 4 - cC];
                    ull w5 = sTab[t + 5], w6 = sTab[t + 6];
                    #pragma unroll
                    for (int r = 0; r < 8; r += 2)
                        abc(vre[r], vim[r], vre[r + 1], vim[r + 1],
                            w0, gi, gin, g1, g1n, w5, w6);
                }
                {   // gate D (intra-register lanes)
                    const int t = t7 + 21;
                    ull p1 = sTab[t + 0], p2e = sTab[t + 1 + cD];
                    ull p3e = sTab[t + 3 + cD], p3n = sTab[t + 4 - cD];
                    ull p4 = sTab[t + 5], p4n = sTab[t + 6];
                    #pragma unroll
                    for (int r = 0; r < 8; r++)
                        dgate(vre[r], vim[r], p1, p2e, p3e, p3n, p4, p4n);
                }
                #pragma unroll
                for (int r = 0; r < 8; r++) {
                    unsigned a = sb ^ ((r & 4) ? wA : 0u) ^ ((r & 2) ? wB : 0u)
                                    ^ ((r & 1) ? wC : 0u);
                    float r0, r1, i0, i1;
                    unpk2(vre[r], r0, r1);
                    unpk2(vim[r], i0, i1);
                    sRe[a] = r0; sRe[a ^ wD] = r1;
                    sIm[a] = i0; sIm[a ^ wD] = i1;
                }
            }
            __syncthreads();
        }
    }

    // ---- stage 4: probabilities -> <Z_q> with permuted sign masks ----
    // sign of Z_q at physical p = (-1)^parity(cROWA[6][11-q] & p)
    float e[NQ];
    #pragma unroll
    for (int q = 0; q < NQ; q++) e[q] = 0.0f;

    #pragma unroll
    for (int lo = 0; lo < APT; lo++) {
        unsigned p = tid + lo * THREADS;
        unsigned idx = S2(p);
        float re = sRe[idx], im = sIm[idx];
        float pr = fmaf(re, re, im * im);
        #pragma unroll
        for (int q = 0; q < NQ; q++)
            e[q] += (__popc(cROWA[NLAYERS][11 - q] & p) & 1) ? -pr : pr;
    }

    #pragma unroll
    for (int q = 0; q < NQ; q++) {
        float v = e[q];
        #pragma unroll
        for (int off = 16; off > 0; off >>= 1)
            v += __shfl_down_sync(0xffffffffu, v, off);
        if ((tid & 31) == 0) atomicAdd(&sExp[q], v);
    }
    __syncthreads();

    // ---- stage 5: readout mitigation, closed form ----
    // M = J - I => M^-1 = J/(n-1) - I ; out_q = (E+12)/11 - e_q - 2
    if (tid < NQ) {
        float E = 0.0f;
        #pragma unroll
        for (int q = 0; q < NQ; q++) E += sExp[q];
        out[b * NQ + tid] = (E + 12.0f) * (1.0f / 11.0f) - sExp[tid] - 2.0f;
    }
}

extern "C" void kernel_launch(void* const* d_in, const int* in_sizes, int n_in,
                              void* d_out, int out_size) {
    const float* x      = (const float*)d_in[0];
    const float* params = (const float*)d_in[1];
    if (n_in >= 2 && in_sizes[0] == NLAYERS * NQ * 3) {
        x      = (const float*)d_in[1];
        params = (const float*)d_in[0];
    }
    cudaFuncSetAttribute(qsim_kernel,
                         cudaFuncAttributePreferredSharedMemoryCarveout, 100);
    int nblk = out_size / NQ;   // 768
    qsim_kernel<<<nblk, THREADS>>>(x, params, (float*)d_out);
}

// round 14
// speedup vs baseline: 1.3124x; 1.3124x over previous
#include <cuda_runtime.h>

#define NQ       12
#define DIM      4096            // 2^12
#define NLAYERS  6
#define NGATES   (NLAYERS * NQ)  // 72
#define THREADS  128
#define APT      (DIM / THREADS) // 32 amplitudes per thread

typedef unsigned long long ull;

// Bank-conflict-avoiding layout: amplitude p lives at sAmp[SWZ(p)].
// GF(2)-linear and invertible: SWZ(a^b) = SWZ(a)^SWZ(b).
#define SWZ(p) ((p) ^ (((p) >> 4) & 0xFu))

// GF(2) matrices of the CNOT-chain map per layer (verified: rowA.colB = I,
// leading bit of cCOLB[l][q] is q). cROWA[l][j] = row j of T^l; cCOLB = col of T^-l.
__constant__ unsigned cROWA[NLAYERS + 1][NQ] = {
    {0x001,0x002,0x004,0x008,0x010,0x020,0x040,0x080,0x100,0x200,0x400,0x800},
    {0xFFF,0xFFE,0xFFC,0xFF8,0xFF0,0xFE0,0xFC0,0xF80,0xF00,0xE00,0xC00,0x800},
    {0x555,0xAAA,0x554,0xAA8,0x550,0xAA0,0x540,0xA80,0x500,0xA00,0x400,0x800},
    {0x333,0x666,0xCCC,0x998,0x330,0x660,0xCC0,0x980,0x300,0x600,0xC00,0x800},
    {0x111,0x222,0x444,0x888,0x110,0x220,0x440,0x880,0x100,0x200,0x400,0x800},
    {0xF0F,0xE1E,0xC3C,0x878,0x0F0,0x1E0,0x3C0,0x780,0xF00,0xE00,0xC00,0x800},
    {0x505,0xA0A,0x414,0x828,0x050,0x0A0,0x140,0x280,0x500,0xA00,0x400,0x800},
};
__constant__ unsigned cCOLB[NLAYERS][NQ] = {
    {0x001,0x002,0x004,0x008,0x010,0x020,0x040,0x080,0x100,0x200,0x400,0x800},
    {0x001,0x003,0x006,0x00C,0x018,0x030,0x060,0x0C0,0x180,0x300,0x600,0xC00},
    {0x001,0x002,0x005,0x00A,0x014,0x028,0x050,0x0A0,0x140,0x280,0x500,0xA00},
    {0x001,0x003,0x007,0x00F,0x01E,0x03C,0x078,0x0F0,0x1E0,0x3C0,0x780,0xF00},
    {0x001,0x002,0x004,0x008,0x011,0x022,0x044,0x088,0x110,0x220,0x440,0x880},
    {0x001,0x003,0x006,0x00C,0x019,0x033,0x066,0x0CC,0x198,0x330,0x660,0xCC0},
};

// Z-sign masks in physical space: cROWA[6][11-q] for q = 0..11 (hard constants).
__constant__ unsigned cZMASK[NQ] = {
    0x800,0x400,0xA00,0x500,0x280,0x140,0x0A0,0x050,0x828,0x414,0xA0A,0x505
};

// ---- packed f32x2 primitives (Blackwell FFMA2 path) ----
__device__ __forceinline__ ull f2mul(ull a, ull b) {
    ull d; asm("mul.rn.f32x2 %0, %1, %2;" : "=l"(d) : "l"(a), "l"(b)); return d;
}
__device__ __forceinline__ ull f2fma(ull a, ull b, ull c) {
    ull d; asm("fma.rn.f32x2 %0, %1, %2, %3;" : "=l"(d) : "l"(a), "l"(b), "l"(c)); return d;
}
__device__ __forceinline__ ull f2swap(ull v) {  // (re,im) -> (im,re)
    ull d;
    asm("{\n\t.reg .b32 lo, hi;\n\tmov.b64 {lo, hi}, %1;\n\tmov.b64 %0, {hi, lo};\n\t}"
        : "=l"(d) : "l"(v));
    return d;
}
__device__ __forceinline__ ull packf2(float lo, float hi) {
    return (ull)__float_as_uint(lo) | ((ull)__float_as_uint(hi) << 32);
}
__device__ __forceinline__ void unpk2(ull v, float& lo, float& hi) {
    asm("mov.b64 {%0, %1}, %2;" : "=f"(lo), "=f"(hi) : "l"(v));
}

// One complex 2x2 butterfly on packed (re,im) amplitudes.
// Exploits Rot symmetry: G11 = conj(G00), G10 = -conj(G01).
__device__ __forceinline__ void bf(ull& x0, ull& x1,
                                   ull r0, ull im, ull rm, ull i1v,
                                   ull ra, ull ia) {
    ull s0 = f2swap(x0), s1 = f2swap(x1);
    ull o0 = f2mul(r0, x0);
    o0 = f2fma(im,  s0, o0);
    o0 = f2fma(rm,  x1, o0);
    o0 = f2fma(i1v, s1, o0);
    ull o1 = f2mul(ra, x0);
    o1 = f2fma(i1v, s0, o1);
    o1 = f2fma(r0,  x1, o1);
    o1 = f2fma(ia,  s1, o1);
    x0 = o0; x1 = o1;
}

// Apply the 4 fused gates of one pass to v[16] (coeff base g6, parities c*).
__device__ __forceinline__ void apply4(ull* v, const ull* __restrict__ sGateP,
                                       int g6, unsigned cA, unsigned cB,
                                       unsigned cC, unsigned cD) {
    {   // gate A (group bit 3); orientation via index shifts on 6-word table
        ull r0 = sGateP[g6 + 0],        im = sGateP[g6 + 1 + cA];
        ull ia = sGateP[g6 + 2 - cA],   rm = sGateP[g6 + 3 + cA];
        ull ra = sGateP[g6 + 4 - cA],   i1 = sGateP[g6 + 5];
        #pragma unroll
        for (int k = 0; k < 8; k++)
            bf(v[k], v[k + 8], r0, im, rm, i1, ra, ia);
    }
    {   // gate B (group bit 2)
        const int gb = g6 + 6;
        ull r0 = sGateP[gb + 0],        im = sGateP[gb + 1 + cB];
        ull ia = sGateP[gb + 2 - cB],   rm = sGateP[gb + 3 + cB];
        ull ra = sGateP[gb + 4 - cB],   i1 = sGateP[gb + 5];
        #pragma unroll
        for (int h = 0; h < 16; h += 8)
            #pragma unroll
            for (int k = 0; k < 4; k++)
                bf(v[h + k], v[h + k + 4], r0, im, rm, i1, ra, ia);
    }
    {   // gate C (group bit 1)
        const int gb = g6 + 12;
        ull r0 = sGateP[gb + 0],        im = sGateP[gb + 1 + cC];
        ull ia = sGateP[gb + 2 - cC],   rm = sGateP[gb + 3 + cC];
        ull ra = sGateP[gb + 4 - cC],   i1 = sGateP[gb + 5];
        #pragma unroll
        for (int h = 0; h < 16; h += 4)
            #pragma unroll
            for (int k = 0; k < 2; k++)
                bf(v[h + k], v[h + k + 2], r0, im, rm, i1, ra, ia);
    }
    {   // gate D (group bit 0)
        const int gb = g6 + 18;
        ull r0 = sGateP[gb + 0],        im = sGateP[gb + 1 + cD];
        ull ia = sGateP[gb + 2 - cD],   rm = sGateP[gb + 3 + cD];
        ull ra = sGateP[gb + 4 - cD],   i1 = sGateP[gb + 5];
        #pragma unroll
        for (int k = 0; k < 16; k += 2)
            bf(v[k], v[k + 1], r0, im, rm, i1, ra, ia);
    }
}

__global__ __launch_bounds__(THREADS, 6)
void qsim_kernel(const float* __restrict__ x,
                 const float* __restrict__ params,
                 float* __restrict__ out) {
    __shared__ ull    sAmp[DIM];            // 32 KB statevector, packed (re,im), swizzled
    __shared__ ull    sGateP[NGATES * 6];   // 3.4 KB: {r0, i0, i0s, r1, r1n, i1} per gate
    __shared__ float  sc[NQ], ssn[NQ];      // cos(x/2), sin(x/2)
    __shared__ float2 sL[32];               // product table, qubits 7..11
    __shared__ float  sExp[NQ];             // <Z_q> accumulators

    float2* sAmpF = reinterpret_cast<float2*>(sAmp);

    const int tid = threadIdx.x;
    const int b   = blockIdx.x;

    // ---- stage 0: trig + compressed packed gate table ----
    if (tid < NQ) {
        float xv = x[b * NQ + tid];
        sc[tid]   = cosf(0.5f * xv);
        ssn[tid]  = sinf(0.5f * xv);
        sExp[tid] = 0.0f;
    }
    if (tid < NGATES) {
        float phi = params[tid * 3 + 0];
        float th  = params[tid * 3 + 1];
        float om  = params[tid * 3 + 2];
        float ct = cosf(0.5f * th), st = sinf(0.5f * th);
        float aa = 0.5f * (phi + om), bb = 0.5f * (phi - om);
        float ca = cosf(aa), sa = sinf(aa);
        float cb = cosf(bb), sb = sinf(bb);
        // G00 = (gr0, gi0) = (ca ct, -sa ct); G01 = (gr1, gi1) = (-cb st, -sb st)
        // G10 = -conj(G01); G11 = conj(G00)
        float gr0 = ca * ct, gi0 = -sa * ct;
        float gr1 = -cb * st, gi1 = -sb * st;
        int tb = tid * 6;
        sGateP[tb + 0] = packf2( gr0,  gr0);   // r0
        sGateP[tb + 1] = packf2(-gi0,  gi0);   // i0
        sGateP[tb + 2] = packf2( gi0, -gi0);   // i0s = swap(i0)  (i-coef of G11)
        sGateP[tb + 3] = packf2( gr1,  gr1);   // r1
        sGateP[tb + 4] = packf2(-gr1, -gr1);   // r1n (real of G10)
        sGateP[tb + 5] = packf2(-gi1,  gi1);   // i1  (i-coef of G01 and G10)
    }
    __syncthreads();

    // ---- stage 1: low-5-bit product table (qubits 7..11 <-> bits 4..0) ----
    if (tid < 32) {
        float2 v = make_float2(1.0f, 0.0f);
        #pragma unroll
        for (int j = 0; j < 5; j++) {
            int q   = 7 + j;
            int bit = (tid >> (4 - j)) & 1;
            v = bit ? make_float2(v.y * ssn[q], -v.x * ssn[q])  // v * (-i sin)
                    : make_float2(v.x * sc[q],   v.y * sc[q]);  // v * cos
        }
        sL[tid] = v;
    }
    __syncthreads();

    // ---- stage 2: direct product-state init (RX embedding on |0..0>) ----
    {
        float2 h = make_float2(1.0f, 0.0f);
        #pragma unroll
        for (int j = 0; j < 7; j++) {
            int bit = (tid >> (6 - j)) & 1;
            h = bit ? make_float2(h.y * ssn[j], -h.x * ssn[j])
                    : make_float2(h.x * sc[j],   h.y * sc[j]);
        }
        #pragma unroll
        for (int lo = 0; lo < 32; lo++) {
            unsigned p = tid * APT + lo;
            float2 g = sL[lo];
            float2 r = make_float2(fmaf(h.x, g.x, -h.y * g.y),
                                   fmaf(h.x, g.y,  h.y * g.x));
            sAmpF[SWZ(p)] = r;
        }
    }
    __syncthreads();

    // ---- stage 3: variational layers; 4 gates fused, CNOTs folded into masks.
    //      Final pass (l=5, qp=8) is fused with measurement below. ----
    for (int l = 0; l < NLAYERS; l++) {
        #pragma unroll
        for (int qp = 0; qp < NQ; qp += 4) {
            if (l == NLAYERS - 1 && qp == 8) continue;   // handled in stage 4
            const int jA = 11 - qp;
            const int pb = 8 - qp;                 // pivot block low bit: 8,4,0
            const unsigned rA = cROWA[l][jA],     rB = cROWA[l][jA - 1];
            const unsigned rC = cROWA[l][jA - 2], rD = cROWA[l][jA - 3];
            const unsigned wA = SWZ(cCOLB[l][jA]),     wB = SWZ(cCOLB[l][jA - 1]);
            const unsigned wC = SWZ(cCOLB[l][jA - 2]), wD = SWZ(cCOLB[l][jA - 3]);
            const unsigned lomask = (pb > 0) ? ((1u << pb) - 1u) : 0u;
            const int g6 = (l * NQ + qp) * 6;      // compressed-coeff base (gate A)

            #pragma unroll
            for (int it = 0; it < DIM / 16 / THREADS; it++) {  // 2 groups/thread
                unsigned g   = tid + it * THREADS;             // 8-bit coset id
                unsigned rep = ((g >> pb) << (pb + 4)) | (g & lomask);
                const unsigned sb = SWZ(rep);
                const unsigned cA = __popc(rA & rep) & 1u;
                const unsigned cB = __popc(rB & rep) & 1u;
                const unsigned cC = __popc(rC & rep) & 1u;
                const unsigned cD = __popc(rD & rep) & 1u;

                ull v[16];
                #pragma unroll
                for (int k = 0; k < 16; k++) {
                    unsigned off = ((k & 8) ? wA : 0u) ^ ((k & 4) ? wB : 0u)
                                 ^ ((k & 2) ? wC : 0u) ^ ((k & 1) ? wD : 0u);
                    v[k] = sAmp[sb ^ off];
                }
                apply4(v, sGateP, g6, cA, cB, cC, cD);
                #pragma unroll
                for (int k = 0; k < 16; k++) {
                    unsigned off = ((k & 8) ? wA : 0u) ^ ((k & 4) ? wB : 0u)
                                 ^ ((k & 2) ? wC : 0u) ^ ((k & 1) ? wD : 0u);
                    sAmp[sb ^ off] = v[k];
                }
            }
            __syncthreads();
        }
    }

    // ---- stage 4: final pass (l=5, qp=8) fused with measurement ----
    // After gates, compute group probs and a 16-pt WHT; then
    // e_q = (-1)^parity(cZMASK[q] & rep) * W[t(q)],
    // t(q) = 0 for q<8; 8,12,14,15 for q = 8,9,10,11 (derived from T).
    {
        const int l = NLAYERS - 1, qp = 8;
        const int jA = 11 - qp;                    // 3
        const unsigned mA = cCOLB[l][jA],     mB = cCOLB[l][jA - 1];
        const unsigned mC = cCOLB[l][jA - 2], mD = cCOLB[l][jA - 3];
        const unsigned rA = cROWA[l][jA],     rB = cROWA[l][jA - 1];
        const unsigned rC = cROWA[l][jA - 2], rD = cROWA[l][jA - 3];
        const unsigned wA = SWZ(mA), wB = SWZ(mB);
        const unsigned wC = SWZ(mC), wD = SWZ(mD);
        const int g6 = (l * NQ + qp) * 6;

        float e[NQ];
        #pragma unroll
        for (int q = 0; q < NQ; q++) e[q] = 0.0f;

        #pragma unroll
        for (int it = 0; it < DIM / 16 / THREADS; it++) {
            unsigned g   = tid + it * THREADS;
            unsigned rep = g << 4;                 // pb = 0
            const unsigned sb = SWZ(rep);
            const unsigned cA = __popc(rA & rep) & 1u;
            const unsigned cB = __popc(rB & rep) & 1u;
            const unsigned cC = __popc(rC & rep) & 1u;
            const unsigned cD = __popc(rD & rep) & 1u;

            ull v[16];
            #pragma unroll
            for (int k = 0; k < 16; k++) {
                unsigned off = ((k & 8) ? wA : 0u) ^ ((k & 4) ? wB : 0u)
                             ^ ((k & 2) ? wC : 0u) ^ ((k & 1) ? wD : 0u);
                v[k] = sAmp[sb ^ off];
            }
            apply4(v, sGateP, g6, cA, cB, cC, cD);

            // probabilities (no store-back needed)
            float w[16];
            #pragma unroll
            for (int k = 0; k < 16; k++) {
                ull pp = f2mul(v[k], v[k]);
                float lo, hi; unpk2(pp, lo, hi);
                w[k] = lo + hi;
            }
            // 16-point WHT: W[t] = sum_k (-1)^popc(k&t) p_k
            #pragma unroll
            for (int s = 1; s < 16; s <<= 1) {
                #pragma unroll
                for (int k = 0; k < 16; k++) {
                    if (!(k & s)) {
                        float a0 = w[k], a1 = w[k | s];
                        w[k] = a0 + a1;
                        w[k | s] = a0 - a1;
                    }
                }
            }
            // accumulate e_q with compile-time WHT indices
            const int TI[NQ] = {0,0,0,0,0,0,0,0,8,12,14,15};
            #pragma unroll
            for (int q = 0; q < NQ; q++) {
                float val = w[TI[q]];
                e[q] += (__popc(cZMASK[q] & rep) & 1) ? -val : val;
            }
        }

        #pragma unroll
        for (int q = 0; q < NQ; q++) {
            float v2 = e[q];
            #pragma unroll
            for (int off = 16; off > 0; off >>= 1)
                v2 += __shfl_down_sync(0xffffffffu, v2, off);
            if ((tid & 31) == 0) atomicAdd(&sExp[q], v2);
        }
    }
    __syncthreads();

    // ---- stage 5: readout mitigation, closed form ----
    // M = J - I => M^-1 = J/(n-1) - I ; out_q = (E+12)/11 - e_q - 2
    if (tid < NQ) {
        float E = 0.0f;
        #pragma unroll
        for (int q = 0; q < NQ; q++) E += sExp[q];
        out[b * NQ + tid] = (E + 12.0f) * (1.0f / 11.0f) - sExp[tid] - 2.0f;
    }
}

extern "C" void kernel_launch(void* const* d_in, const int* in_sizes, int n_in,
                              void* d_out, int out_size) {
    const float* x      = (const float*)d_in[0];
    const float* params = (const float*)d_in[1];
    if (n_in >= 2 && in_sizes[0] == NLAYERS * NQ * 3) {
        x      = (const float*)d_in[1];
        params = (const float*)d_in[0];
    }
    cudaFuncSetAttribute(qsim_kernel,
                         cudaFuncAttributePreferredSharedMemoryCarveout, 100);
    int nblk = out_size / NQ;   // 768
    qsim_kernel<<<nblk, THREADS>>>(x, params, (float*)d_out);
}